// round 4
// baseline (speedup 1.0000x reference)
#include <cuda_runtime.h>
#include <cstdint>

// ============================================================================
// y[m,o] = fq_tok(x)[m,:] . fq_ch(w)[o,:] + b[o]
//   fq value = q * s, q integer in [-128,127]:
//   y[m,o] = sx[m]*sw[o]*(sum_k qx[m,k]*qw[o,k]) + b[o]
// Exact int8 GEMM. Legacy mma.sync tensor path is HW-capped at ~256 MACs/SM/cyc
// on sm_103 (tcgen05 unavailable: harness emits compute_103 family PTX), so we
// ALSO run a dp4a (ALU-pipe) flavor on a slice of M, co-resident per SM with
// tensor-flavor CTAs to overlap the two pipes.
// M = 8192 (derived), N = 4096, K = 4096.
// Split: m-tiles 0..51 -> tensor mma, m-tiles 52..63 -> dp4a (3/16 of work).
// ============================================================================

#define MAX_M 8192
#define NN 4096
#define KK 4096

__device__ int8_t g_qx[(size_t)MAX_M * KK];   // 32 MB
__device__ int8_t g_qw[(size_t)NN * KK];      // 16 MB
__device__ float g_sx[MAX_M];
__device__ float g_sw[NN];

// ---------------------------------------------------------------------------
// PTX helpers (family-portable, sm_80+ baseline ISA)
// ---------------------------------------------------------------------------
__device__ __forceinline__ uint32_t smem_u32(const void* p) {
    uint32_t a;
    asm("{ .reg .u64 t; cvta.to.shared.u64 t, %1; cvt.u32.u64 %0, t; }" : "=r"(a) : "l"(p));
    return a;
}

#define CP_ASYNC16(smem, gptr) \
    asm volatile("cp.async.cg.shared.global [%0], [%1], 16;" \
        :: "r"((uint32_t)(smem)), "l"(gptr) : "memory")
#define CP_COMMIT() asm volatile("cp.async.commit_group;" ::: "memory")
#define CP_WAIT(n)  asm volatile("cp.async.wait_group %0;" :: "n"(n) : "memory")

#define LDSM_X4(r0, r1, r2, r3, addr) \
    asm volatile("ldmatrix.sync.aligned.m8n8.x4.shared.b16 {%0,%1,%2,%3}, [%4];" \
        : "=r"(r0), "=r"(r1), "=r"(r2), "=r"(r3) : "r"((uint32_t)(addr)))

#define MMA_S8(d, a0, a1, a2, a3, b0, b1) \
    asm volatile("mma.sync.aligned.m16n8k32.row.col.s32.s8.s8.s32 " \
        "{%0,%1,%2,%3},{%4,%5,%6,%7},{%8,%9},{%0,%1,%2,%3};" \
        : "+r"((d)[0]), "+r"((d)[1]), "+r"((d)[2]), "+r"((d)[3]) \
        : "r"(a0), "r"(a1), "r"(a2), "r"(a3), "r"(b0), "r"(b1))

// ---------------------------------------------------------------------------
// Kernel 1: fused per-row symmetric fake-quant for BOTH x and w -> int8+scale.
// ---------------------------------------------------------------------------
__global__ __launch_bounds__(256) void quant_rows(const float* __restrict__ x,
                                                  const float* __restrict__ w,
                                                  int M) {
    const int bid = blockIdx.x;
    const bool is_x = bid < M;
    const int row = is_x ? bid : bid - M;
    const float* in = is_x ? x : w;
    int8_t* qout = is_x ? g_qx : g_qw;
    float* sout = is_x ? g_sx : g_sw;

    const int t = threadIdx.x;
    const float4* src = reinterpret_cast<const float4*>(in) + (size_t)row * (KK / 4);

    float4 v[4];
    float am = 0.f;
#pragma unroll
    for (int j = 0; j < 4; j++) {
        v[j] = src[t + j * 256];
        am = fmaxf(am, fmaxf(fmaxf(fabsf(v[j].x), fabsf(v[j].y)),
                             fmaxf(fabsf(v[j].z), fabsf(v[j].w))));
    }
#pragma unroll
    for (int o = 16; o; o >>= 1) am = fmaxf(am, __shfl_xor_sync(0xffffffffu, am, o));

    __shared__ float s_red[8];
    __shared__ float s_scale;
    if ((t & 31) == 0) s_red[t >> 5] = am;
    __syncthreads();
    if (t < 8) {
        float a = s_red[t];
#pragma unroll
        for (int o = 4; o; o >>= 1) a = fmaxf(a, __shfl_xor_sync(0xffu, a, o));
        if (t == 0) {
            float sc = fmaxf(a / 127.0f, 1e-8f);
            s_scale = sc;
            sout[row] = sc;
        }
    }
    __syncthreads();
    const float inv = 1.0f / s_scale;

    uint32_t* qrow = reinterpret_cast<uint32_t*>(qout + (size_t)row * KK);
#pragma unroll
    for (int j = 0; j < 4; j++) {
        int q0 = min(max(__float2int_rn(v[j].x * inv), -128), 127);
        int q1 = min(max(__float2int_rn(v[j].y * inv), -128), 127);
        int q2 = min(max(__float2int_rn(v[j].z * inv), -128), 127);
        int q3 = min(max(__float2int_rn(v[j].w * inv), -128), 127);
        qrow[t + j * 256] = (uint32_t)(q0 & 0xff) | ((uint32_t)(q1 & 0xff) << 8) |
                            ((uint32_t)(q2 & 0xff) << 16) | ((uint32_t)q3 << 24);
    }
}

// ---------------------------------------------------------------------------
// Kernel 2: mixed-flavor int8 GEMM. Both flavors: BM=BN=128, BK=64,
// 4-stage cp.async, 80B-padded smem rows, 256 threads, 2 CTAs/SM.
// Flavor T (13/16 of CTAs): warp-tile 32x64 mma.sync s8 (tensor pipe).
// Flavor D (3/16 of CTAs): 8x8-per-thread dp4a (alu pipe).
// ---------------------------------------------------------------------------
#define STAGES 4
#define STAGE_BYTES (2 * 128 * 80)

__global__ __launch_bounds__(256, 2) void gemm_mixed(const float* __restrict__ bias,
                                                     float* __restrict__ out) {
    constexpr int KT = KK / 64;   // 64 main-loop iterations

    extern __shared__ char sm[];
    __shared__ float s_sw[128];
    __shared__ float s_bias[128];

    const int t = threadIdx.x;
    const int bid = blockIdx.x;
    const int grp = bid >> 4;
    const int rem = bid & 15;
    const bool is_dp = rem >= 13;

    int mt, nt;
    if (!is_dp) {
        const int ti = grp * 13 + rem;
        mt = ti >> 5;
        nt = ti & 31;
    } else {
        const int di = grp * 3 + (rem - 13);
        mt = 52 + (di >> 5);
        nt = di & 31;
    }
    const int m0 = mt * 128;
    const int n0 = nt * 128;

    if (t < 128) {
        s_sw[t] = g_sw[n0 + t];
        s_bias[t] = bias[n0 + t];
    }

    const int8_t* gA = g_qx + (size_t)m0 * KK;
    const int8_t* gB = g_qw + (size_t)n0 * KK;
    const uint32_t smbase = smem_u32(sm);

    // cp.async mapping: 512 16B chunks per tile, 2 per thread per tile.
    const int crow = t >> 2;
    const int ccol = t & 3;

    auto issue = [&](int it) {
        const int s = it % STAGES;
        const uint32_t sa = smbase + s * STAGE_BYTES;
        const uint32_t sb = sa + 128 * 80;
        const int koff = it * 64 + ccol * 16;
#pragma unroll
        for (int j = 0; j < 2; j++) {
            const int r = crow + j * 64;
            const uint32_t so = (uint32_t)r * 80u + (uint32_t)ccol * 16u;
            CP_ASYNC16(sa + so, gA + (size_t)r * KK + koff);
            CP_ASYNC16(sb + so, gB + (size_t)r * KK + koff);
        }
    };

#pragma unroll
    for (int it = 0; it < STAGES - 1; ++it) {
        issue(it);
        CP_COMMIT();
    }

    if (!is_dp) {
        // ================= Tensor flavor (round-2 proven config) =============
        const int lane = t & 31;
        const int wid = t >> 5;
        const int warpM = wid & 3;
        const int warpN = wid >> 2;

        int acc[2][8][4];
#pragma unroll
        for (int a = 0; a < 2; a++)
#pragma unroll
            for (int b = 0; b < 8; b++)
#pragma unroll
                for (int i = 0; i < 4; i++) acc[a][b][i] = 0;

        const uint32_t a_off =
            (uint32_t)(warpM * 32 + (lane & 15)) * 80u + (uint32_t)(lane >> 4) * 16u;
        const uint32_t b_off =
            (uint32_t)(warpN * 64 + (lane & 7) + ((lane >> 4) & 1) * 8) * 80u +
            (uint32_t)((lane >> 3) & 1) * 16u;

        for (int it = 0; it < KT; ++it) {
            CP_WAIT(STAGES - 2);
            __syncthreads();
            const int nit = it + STAGES - 1;
            if (nit < KT) issue(nit);
            CP_COMMIT();

            const uint32_t sa = smbase + (it % STAGES) * STAGE_BYTES;
            const uint32_t sb = sa + 128 * 80;

#pragma unroll
            for (int s = 0; s < 2; ++s) {
                uint32_t a[2][4];
#pragma unroll
                for (int mtl = 0; mtl < 2; mtl++) {
                    LDSM_X4(a[mtl][0], a[mtl][1], a[mtl][2], a[mtl][3],
                            sa + a_off + (uint32_t)mtl * (16u * 80u) + (uint32_t)s * 32u);
                }
#pragma unroll
                for (int np = 0; np < 4; np++) {
                    uint32_t b0, b1, b2, b3;
                    LDSM_X4(b0, b1, b2, b3,
                            sb + b_off + (uint32_t)np * (16u * 80u) + (uint32_t)s * 32u);
#pragma unroll
                    for (int mtl = 0; mtl < 2; mtl++) {
                        MMA_S8(acc[mtl][2 * np + 0], a[mtl][0], a[mtl][1], a[mtl][2], a[mtl][3], b0, b1);
                        MMA_S8(acc[mtl][2 * np + 1], a[mtl][0], a[mtl][1], a[mtl][2], a[mtl][3], b2, b3);
                    }
                }
            }
        }

        // Epilogue
#pragma unroll
        for (int mtl = 0; mtl < 2; mtl++) {
            const int r0 = warpM * 32 + mtl * 16 + (lane >> 2);
            const float sx0 = g_sx[m0 + r0];
            const float sx1 = g_sx[m0 + r0 + 8];
            float* o0 = out + (size_t)(m0 + r0) * NN + n0;
            float* o1 = o0 + (size_t)8 * NN;
#pragma unroll
            for (int ntl = 0; ntl < 8; ntl++) {
                const int lc = warpN * 64 + ntl * 8 + (lane & 3) * 2;
                const float w0 = s_sw[lc], w1 = s_sw[lc + 1];
                const float bb0 = s_bias[lc], bb1 = s_bias[lc + 1];
                float2 v0, v1;
                v0.x = fmaf((float)acc[mtl][ntl][0] * sx0, w0, bb0);
                v0.y = fmaf((float)acc[mtl][ntl][1] * sx0, w1, bb1);
                v1.x = fmaf((float)acc[mtl][ntl][2] * sx1, w0, bb0);
                v1.y = fmaf((float)acc[mtl][ntl][3] * sx1, w1, bb1);
                *reinterpret_cast<float2*>(o0 + lc) = v0;
                *reinterpret_cast<float2*>(o1 + lc) = v1;
            }
        }
    } else {
        // ================= dp4a flavor (alu pipe) ============================
        const int tr = t >> 4;    // 0..15, owns rows tr*8..tr*8+7
        const int tc = t & 15;    // 0..15, owns cols tc*8..tc*8+7

        int acc[8][8];
#pragma unroll
        for (int r = 0; r < 8; r++)
#pragma unroll
            for (int c = 0; c < 8; c++) acc[r][c] = 0;

        for (int it = 0; it < KT; ++it) {
            CP_WAIT(STAGES - 2);
            __syncthreads();
            const int nit = it + STAGES - 1;
            if (nit < KT) issue(nit);
            CP_COMMIT();

            const uint32_t sa = smbase + (it % STAGES) * STAGE_BYTES;
            const uint32_t sb = sa + 128 * 80;

#pragma unroll
            for (int g = 0; g < 4; g++) {   // 4 groups of 16 K-bytes
                uint4 a4[8];
#pragma unroll
                for (int r = 0; r < 8; r++) {
                    a4[r] = *reinterpret_cast<const uint4*>(
                        sm + (sa - smbase) + (uint32_t)(tr * 8 + r) * 80u + (uint32_t)g * 16u);
                }
#pragma unroll
                for (int c = 0; c < 8; c++) {
                    const uint4 bv = *reinterpret_cast<const uint4*>(
                        sm + (sb - smbase) + (uint32_t)(tc * 8 + c) * 80u + (uint32_t)g * 16u);
#pragma unroll
                    for (int r = 0; r < 8; r++) {
                        int v = __dp4a((int)a4[r].x, (int)bv.x, acc[r][c]);
                        v = __dp4a((int)a4[r].y, (int)bv.y, v);
                        v = __dp4a((int)a4[r].z, (int)bv.z, v);
                        acc[r][c] = __dp4a((int)a4[r].w, (int)bv.w, v);
                    }
                }
            }
        }

        // Epilogue
#pragma unroll
        for (int r = 0; r < 8; r++) {
            const int row = m0 + tr * 8 + r;
            const float sxv = g_sx[row];
            float* orow = out + (size_t)row * NN + n0 + tc * 8;
#pragma unroll
            for (int c = 0; c < 8; c += 4) {
                const int lc = tc * 8 + c;
                float4 o;
                o.x = fmaf((float)acc[r][c + 0] * sxv, s_sw[lc + 0], s_bias[lc + 0]);
                o.y = fmaf((float)acc[r][c + 1] * sxv, s_sw[lc + 1], s_bias[lc + 1]);
                o.z = fmaf((float)acc[r][c + 2] * sxv, s_sw[lc + 2], s_bias[lc + 2]);
                o.w = fmaf((float)acc[r][c + 3] * sxv, s_sw[lc + 3], s_bias[lc + 3]);
                *reinterpret_cast<float4*>(orow + c) = o;
            }
        }
    }
}

// ---------------------------------------------------------------------------
// Launch
// ---------------------------------------------------------------------------
extern "C" void kernel_launch(void* const* d_in, const int* in_sizes, int n_in,
                              void* d_out, int out_size) {
    const float* x = (const float*)d_in[0];   // [M, 4096]
    const float* w = (const float*)d_in[1];   // [4096, 4096]
    const float* b = (const float*)d_in[2];   // [4096]
    float* out = (float*)d_out;               // [M, 4096]

    const int M = in_sizes[0] / KK;           // 8192

    quant_rows<<<M + NN, 256>>>(x, w, M);

    cudaFuncSetAttribute(gemm_mixed, cudaFuncAttributeMaxDynamicSharedMemorySize,
                         STAGES * STAGE_BYTES);

    const int total_tiles = (M / 128) * (NN / 128);   // 2048
    gemm_mixed<<<total_tiles, 256, STAGES * STAGE_BYTES>>>(b, out);
}

// round 5
// speedup vs baseline: 1.2822x; 1.2822x over previous
#include <cuda_runtime.h>
#include <cstdint>

// ============================================================================
// y[m,o] = fq_tok(x)[m,:] . fq_ch(w)[o,:] + b[o]
//   fq value = q * s, q integer in [-128,127]:
//   y[m,o] = sx[m]*sw[o]*(sum_k qx[m,k]*qw[o,k]) + b[o]
// Exact int8 GEMM. Legacy mma.sync tensor pipe is HW-capped ~310 MACs/SM/cyc
// on sm_103 (tcgen05 rejected by family-PTX target), so we overlap it with a
// dp4a (alu-pipe) flavor on a slice of M, co-resident per SM.
// Round-5: dp4a B-tile bank conflicts fixed (column-ownership stride-16
// permutation: across-lane LDS stride 80B -> all 8 phase lanes distinct banks).
// Split: m-tiles 0..43 tensor (11/16), 44..63 dp4a (5/16).
// ============================================================================

#define MAX_M 8192
#define NN 4096
#define KK 4096

__device__ int8_t g_qx[(size_t)MAX_M * KK];   // 32 MB
__device__ int8_t g_qw[(size_t)NN * KK];      // 16 MB
__device__ float g_sx[MAX_M];
__device__ float g_sw[NN];

// ---------------------------------------------------------------------------
// PTX helpers (family-portable, sm_80+ baseline ISA)
// ---------------------------------------------------------------------------
__device__ __forceinline__ uint32_t smem_u32(const void* p) {
    uint32_t a;
    asm("{ .reg .u64 t; cvta.to.shared.u64 t, %1; cvt.u32.u64 %0, t; }" : "=r"(a) : "l"(p));
    return a;
}

#define CP_ASYNC16(smem, gptr) \
    asm volatile("cp.async.cg.shared.global [%0], [%1], 16;" \
        :: "r"((uint32_t)(smem)), "l"(gptr) : "memory")
#define CP_COMMIT() asm volatile("cp.async.commit_group;" ::: "memory")
#define CP_WAIT(n)  asm volatile("cp.async.wait_group %0;" :: "n"(n) : "memory")

#define LDSM_X4(r0, r1, r2, r3, addr) \
    asm volatile("ldmatrix.sync.aligned.m8n8.x4.shared.b16 {%0,%1,%2,%3}, [%4];" \
        : "=r"(r0), "=r"(r1), "=r"(r2), "=r"(r3) : "r"((uint32_t)(addr)))

#define MMA_S8(d, a0, a1, a2, a3, b0, b1) \
    asm volatile("mma.sync.aligned.m16n8k32.row.col.s32.s8.s8.s32 " \
        "{%0,%1,%2,%3},{%4,%5,%6,%7},{%8,%9},{%0,%1,%2,%3};" \
        : "+r"((d)[0]), "+r"((d)[1]), "+r"((d)[2]), "+r"((d)[3]) \
        : "r"(a0), "r"(a1), "r"(a2), "r"(a3), "r"(b0), "r"(b1))

// ---------------------------------------------------------------------------
// Kernel 1: fused per-row symmetric fake-quant for BOTH x and w -> int8+scale.
// ---------------------------------------------------------------------------
__global__ __launch_bounds__(256) void quant_rows(const float* __restrict__ x,
                                                  const float* __restrict__ w,
                                                  int M) {
    const int bid = blockIdx.x;
    const bool is_x = bid < M;
    const int row = is_x ? bid : bid - M;
    const float* in = is_x ? x : w;
    int8_t* qout = is_x ? g_qx : g_qw;
    float* sout = is_x ? g_sx : g_sw;

    const int t = threadIdx.x;
    const float4* src = reinterpret_cast<const float4*>(in) + (size_t)row * (KK / 4);

    float4 v[4];
    float am = 0.f;
#pragma unroll
    for (int j = 0; j < 4; j++) {
        v[j] = src[t + j * 256];
        am = fmaxf(am, fmaxf(fmaxf(fabsf(v[j].x), fabsf(v[j].y)),
                             fmaxf(fabsf(v[j].z), fabsf(v[j].w))));
    }
#pragma unroll
    for (int o = 16; o; o >>= 1) am = fmaxf(am, __shfl_xor_sync(0xffffffffu, am, o));

    __shared__ float s_red[8];
    __shared__ float s_scale;
    if ((t & 31) == 0) s_red[t >> 5] = am;
    __syncthreads();
    if (t < 8) {
        float a = s_red[t];
#pragma unroll
        for (int o = 4; o; o >>= 1) a = fmaxf(a, __shfl_xor_sync(0xffu, a, o));
        if (t == 0) {
            float sc = fmaxf(a / 127.0f, 1e-8f);
            s_scale = sc;
            sout[row] = sc;
        }
    }
    __syncthreads();
    const float inv = 1.0f / s_scale;

    uint32_t* qrow = reinterpret_cast<uint32_t*>(qout + (size_t)row * KK);
#pragma unroll
    for (int j = 0; j < 4; j++) {
        int q0 = min(max(__float2int_rn(v[j].x * inv), -128), 127);
        int q1 = min(max(__float2int_rn(v[j].y * inv), -128), 127);
        int q2 = min(max(__float2int_rn(v[j].z * inv), -128), 127);
        int q3 = min(max(__float2int_rn(v[j].w * inv), -128), 127);
        qrow[t + j * 256] = (uint32_t)(q0 & 0xff) | ((uint32_t)(q1 & 0xff) << 8) |
                            ((uint32_t)(q2 & 0xff) << 16) | ((uint32_t)q3 << 24);
    }
}

// ---------------------------------------------------------------------------
// Kernel 2: mixed-flavor int8 GEMM. Both flavors: BM=BN=128, BK=64,
// 4-stage cp.async, 80B-padded smem rows, 256 threads, 2 CTAs/SM.
// Flavor T (11/16 of CTAs): warp-tile 32x64 mma.sync s8 (tensor pipe).
// Flavor D (5/16 of CTAs): 8x8-per-thread dp4a (alu pipe), conflict-free.
// ---------------------------------------------------------------------------
#define STAGES 4
#define STAGE_BYTES (2 * 128 * 80)

__global__ __launch_bounds__(256, 2) void gemm_mixed(const float* __restrict__ bias,
                                                     float* __restrict__ out) {
    constexpr int KT = KK / 64;   // 64 main-loop iterations

    extern __shared__ char sm[];
    __shared__ float s_sw[128];
    __shared__ float s_bias[128];

    const int t = threadIdx.x;
    const int bid = blockIdx.x;
    const int grp = bid >> 4;
    const int rem = bid & 15;
    const bool is_dp = rem >= 11;

    int mt, nt;
    if (!is_dp) {
        const int ti = grp * 11 + rem;      // 0..1407 -> m-tiles 0..43
        mt = ti >> 5;
        nt = ti & 31;
    } else {
        const int di = grp * 5 + (rem - 11); // 0..639 -> m-tiles 44..63
        mt = 44 + (di >> 5);
        nt = di & 31;
    }
    const int m0 = mt * 128;
    const int n0 = nt * 128;

    if (t < 128) {
        s_sw[t] = g_sw[n0 + t];
        s_bias[t] = bias[n0 + t];
    }

    const int8_t* gA = g_qx + (size_t)m0 * KK;
    const int8_t* gB = g_qw + (size_t)n0 * KK;
    const uint32_t smbase = smem_u32(sm);

    // cp.async mapping: 512 16B chunks per tile, 2 per thread per tile.
    const int crow = t >> 2;
    const int ccol = t & 3;

    auto issue = [&](int it) {
        const int s = it % STAGES;
        const uint32_t sa = smbase + s * STAGE_BYTES;
        const uint32_t sb = sa + 128 * 80;
        const int koff = it * 64 + ccol * 16;
#pragma unroll
        for (int j = 0; j < 2; j++) {
            const int r = crow + j * 64;
            const uint32_t so = (uint32_t)r * 80u + (uint32_t)ccol * 16u;
            CP_ASYNC16(sa + so, gA + (size_t)r * KK + koff);
            CP_ASYNC16(sb + so, gB + (size_t)r * KK + koff);
        }
    };

#pragma unroll
    for (int it = 0; it < STAGES - 1; ++it) {
        issue(it);
        CP_COMMIT();
    }

    if (!is_dp) {
        // ================= Tensor flavor =====================================
        const int lane = t & 31;
        const int wid = t >> 5;
        const int warpM = wid & 3;
        const int warpN = wid >> 2;

        int acc[2][8][4];
#pragma unroll
        for (int a = 0; a < 2; a++)
#pragma unroll
            for (int b = 0; b < 8; b++)
#pragma unroll
                for (int i = 0; i < 4; i++) acc[a][b][i] = 0;

        const uint32_t a_off =
            (uint32_t)(warpM * 32 + (lane & 15)) * 80u + (uint32_t)(lane >> 4) * 16u;
        const uint32_t b_off =
            (uint32_t)(warpN * 64 + (lane & 7) + ((lane >> 4) & 1) * 8) * 80u +
            (uint32_t)((lane >> 3) & 1) * 16u;

        for (int it = 0; it < KT; ++it) {
            CP_WAIT(STAGES - 2);
            __syncthreads();
            const int nit = it + STAGES - 1;
            if (nit < KT) issue(nit);
            CP_COMMIT();

            const uint32_t sa = smbase + (it % STAGES) * STAGE_BYTES;
            const uint32_t sb = sa + 128 * 80;

#pragma unroll
            for (int s = 0; s < 2; ++s) {
                uint32_t a[2][4];
#pragma unroll
                for (int mtl = 0; mtl < 2; mtl++) {
                    LDSM_X4(a[mtl][0], a[mtl][1], a[mtl][2], a[mtl][3],
                            sa + a_off + (uint32_t)mtl * (16u * 80u) + (uint32_t)s * 32u);
                }
#pragma unroll
                for (int np = 0; np < 4; np++) {
                    uint32_t b0, b1, b2, b3;
                    LDSM_X4(b0, b1, b2, b3,
                            sb + b_off + (uint32_t)np * (16u * 80u) + (uint32_t)s * 32u);
#pragma unroll
                    for (int mtl = 0; mtl < 2; mtl++) {
                        MMA_S8(acc[mtl][2 * np + 0], a[mtl][0], a[mtl][1], a[mtl][2], a[mtl][3], b0, b1);
                        MMA_S8(acc[mtl][2 * np + 1], a[mtl][0], a[mtl][1], a[mtl][2], a[mtl][3], b2, b3);
                    }
                }
            }
        }

        // Epilogue
#pragma unroll
        for (int mtl = 0; mtl < 2; mtl++) {
            const int r0 = warpM * 32 + mtl * 16 + (lane >> 2);
            const float sx0 = g_sx[m0 + r0];
            const float sx1 = g_sx[m0 + r0 + 8];
            float* o0 = out + (size_t)(m0 + r0) * NN + n0;
            float* o1 = o0 + (size_t)8 * NN;
#pragma unroll
            for (int ntl = 0; ntl < 8; ntl++) {
                const int lc = warpN * 64 + ntl * 8 + (lane & 3) * 2;
                const float w0 = s_sw[lc], w1 = s_sw[lc + 1];
                const float bb0 = s_bias[lc], bb1 = s_bias[lc + 1];
                float2 v0, v1;
                v0.x = fmaf((float)acc[mtl][ntl][0] * sx0, w0, bb0);
                v0.y = fmaf((float)acc[mtl][ntl][1] * sx0, w1, bb1);
                v1.x = fmaf((float)acc[mtl][ntl][2] * sx1, w0, bb0);
                v1.y = fmaf((float)acc[mtl][ntl][3] * sx1, w1, bb1);
                *reinterpret_cast<float2*>(o0 + lc) = v0;
                *reinterpret_cast<float2*>(o1 + lc) = v1;
            }
        }
    } else {
        // ================= dp4a flavor (alu pipe, conflict-free) =============
        // Thread (tr, tc): rows tr*8..tr*8+7, cols {tc + 16c, c=0..7}.
        // B LDS across-lane stride = 80B -> phase banks all distinct.
        const int tr = t >> 4;    // 0..15
        const int tc = t & 15;    // 0..15

        int acc[8][8];
#pragma unroll
        for (int r = 0; r < 8; r++)
#pragma unroll
            for (int c = 0; c < 8; c++) acc[r][c] = 0;

        for (int it = 0; it < KT; ++it) {
            CP_WAIT(STAGES - 2);
            __syncthreads();
            const int nit = it + STAGES - 1;
            if (nit < KT) issue(nit);
            CP_COMMIT();

            const uint32_t sa_off = (uint32_t)((it % STAGES) * STAGE_BYTES);
            const uint32_t sb_off = sa_off + 128 * 80;

#pragma unroll
            for (int g = 0; g < 4; g++) {   // 4 groups of 16 K-bytes
                uint4 a4[8];
#pragma unroll
                for (int r = 0; r < 8; r++) {
                    a4[r] = *reinterpret_cast<const uint4*>(
                        sm + sa_off + (uint32_t)(tr * 8 + r) * 80u + (uint32_t)g * 16u);
                }
#pragma unroll
                for (int c = 0; c < 8; c++) {
                    const uint4 bv = *reinterpret_cast<const uint4*>(
                        sm + sb_off + (uint32_t)(tc + 16 * c) * 80u + (uint32_t)g * 16u);
#pragma unroll
                    for (int r = 0; r < 8; r++) {
                        int v = __dp4a((int)a4[r].x, (int)bv.x, acc[r][c]);
                        v = __dp4a((int)a4[r].y, (int)bv.y, v);
                        v = __dp4a((int)a4[r].z, (int)bv.z, v);
                        acc[r][c] = __dp4a((int)a4[r].w, (int)bv.w, v);
                    }
                }
            }
        }

        // Epilogue (column stride 16 -> scalar stores, coalesced across tc)
#pragma unroll
        for (int r = 0; r < 8; r++) {
            const int row = m0 + tr * 8 + r;
            const float sxv = g_sx[row];
            float* orow = out + (size_t)row * NN + n0;
#pragma unroll
            for (int c = 0; c < 8; c++) {
                const int lc = tc + 16 * c;
                orow[lc] = fmaf((float)acc[r][c] * sxv, s_sw[lc], s_bias[lc]);
            }
        }
    }
}

// ---------------------------------------------------------------------------
// Launch
// ---------------------------------------------------------------------------
extern "C" void kernel_launch(void* const* d_in, const int* in_sizes, int n_in,
                              void* d_out, int out_size) {
    const float* x = (const float*)d_in[0];   // [M, 4096]
    const float* w = (const float*)d_in[1];   // [4096, 4096]
    const float* b = (const float*)d_in[2];   // [4096]
    float* out = (float*)d_out;               // [M, 4096]

    const int M = in_sizes[0] / KK;           // 8192

    quant_rows<<<M + NN, 256>>>(x, w, M);

    cudaFuncSetAttribute(gemm_mixed, cudaFuncAttributeMaxDynamicSharedMemorySize,
                         STAGES * STAGE_BYTES);

    const int total_tiles = (M / 128) * (NN / 128);   // 2048
    gemm_mixed<<<total_tiles, 256, STAGES * STAGE_BYTES>>>(b, out);
}

// round 6
// speedup vs baseline: 1.6534x; 1.2895x over previous
#include <cuda_runtime.h>
#include <cstdint>

// ============================================================================
// y[m,o] = fq_tok(x)[m,:] . fq_ch(w)[o,:] + b[o]
//   fq value = q * s, q integer in [-128,127]:
//   y[m,o] = sx[m]*sw[o]*(sum_k qx[m,k]*qw[o,k]) + b[o]
// Exact int8 GEMM. On sm_103 (family PTX; tcgen05 rejected) the legacy
// mma.sync tensor pipe and the dp4a (fma) pipe each sustain ~256 MACs/SM/cyc.
// Round 6: HYBRID CTA — warps 0-3 drive the tensor pipe on rows 0-63 of each
// 128x128 tile, warps 4-7 drive dp4a on rows 64-127. Both pipes saturated on
// every SM, shared SMEM tiles, no straggler tail.
// M = 8192 (derived), N = 4096, K = 4096.
// ============================================================================

#define MAX_M 8192
#define NN 4096
#define KK 4096

__device__ int8_t g_qx[(size_t)MAX_M * KK];   // 32 MB
__device__ int8_t g_qw[(size_t)NN * KK];      // 16 MB
__device__ float g_sx[MAX_M];
__device__ float g_sw[NN];

// ---------------------------------------------------------------------------
// PTX helpers (family-portable, sm_80+ baseline ISA)
// ---------------------------------------------------------------------------
__device__ __forceinline__ uint32_t smem_u32(const void* p) {
    uint32_t a;
    asm("{ .reg .u64 t; cvta.to.shared.u64 t, %1; cvt.u32.u64 %0, t; }" : "=r"(a) : "l"(p));
    return a;
}

#define CP_ASYNC16(smem, gptr) \
    asm volatile("cp.async.cg.shared.global [%0], [%1], 16;" \
        :: "r"((uint32_t)(smem)), "l"(gptr) : "memory")
#define CP_COMMIT() asm volatile("cp.async.commit_group;" ::: "memory")
#define CP_WAIT(n)  asm volatile("cp.async.wait_group %0;" :: "n"(n) : "memory")

#define LDSM_X4(r0, r1, r2, r3, addr) \
    asm volatile("ldmatrix.sync.aligned.m8n8.x4.shared.b16 {%0,%1,%2,%3}, [%4];" \
        : "=r"(r0), "=r"(r1), "=r"(r2), "=r"(r3) : "r"((uint32_t)(addr)))

#define MMA_S8(d, a0, a1, a2, a3, b0, b1) \
    asm volatile("mma.sync.aligned.m16n8k32.row.col.s32.s8.s8.s32 " \
        "{%0,%1,%2,%3},{%4,%5,%6,%7},{%8,%9},{%0,%1,%2,%3};" \
        : "+r"((d)[0]), "+r"((d)[1]), "+r"((d)[2]), "+r"((d)[3]) \
        : "r"(a0), "r"(a1), "r"(a2), "r"(a3), "r"(b0), "r"(b1))

// ---------------------------------------------------------------------------
// Kernel 1: fused per-row symmetric fake-quant for BOTH x and w -> int8+scale.
// ---------------------------------------------------------------------------
__global__ __launch_bounds__(256) void quant_rows(const float* __restrict__ x,
                                                  const float* __restrict__ w,
                                                  int M) {
    const int bid = blockIdx.x;
    const bool is_x = bid < M;
    const int row = is_x ? bid : bid - M;
    const float* in = is_x ? x : w;
    int8_t* qout = is_x ? g_qx : g_qw;
    float* sout = is_x ? g_sx : g_sw;

    const int t = threadIdx.x;
    const float4* src = reinterpret_cast<const float4*>(in) + (size_t)row * (KK / 4);

    float4 v[4];
    float am = 0.f;
#pragma unroll
    for (int j = 0; j < 4; j++) {
        v[j] = src[t + j * 256];
        am = fmaxf(am, fmaxf(fmaxf(fabsf(v[j].x), fabsf(v[j].y)),
                             fmaxf(fabsf(v[j].z), fabsf(v[j].w))));
    }
#pragma unroll
    for (int o = 16; o; o >>= 1) am = fmaxf(am, __shfl_xor_sync(0xffffffffu, am, o));

    __shared__ float s_red[8];
    __shared__ float s_scale;
    if ((t & 31) == 0) s_red[t >> 5] = am;
    __syncthreads();
    if (t < 8) {
        float a = s_red[t];
#pragma unroll
        for (int o = 4; o; o >>= 1) a = fmaxf(a, __shfl_xor_sync(0xffu, a, o));
        if (t == 0) {
            float sc = fmaxf(a / 127.0f, 1e-8f);
            s_scale = sc;
            sout[row] = sc;
        }
    }
    __syncthreads();
    const float inv = 1.0f / s_scale;

    uint32_t* qrow = reinterpret_cast<uint32_t*>(qout + (size_t)row * KK);
#pragma unroll
    for (int j = 0; j < 4; j++) {
        int q0 = min(max(__float2int_rn(v[j].x * inv), -128), 127);
        int q1 = min(max(__float2int_rn(v[j].y * inv), -128), 127);
        int q2 = min(max(__float2int_rn(v[j].z * inv), -128), 127);
        int q3 = min(max(__float2int_rn(v[j].w * inv), -128), 127);
        qrow[t + j * 256] = (uint32_t)(q0 & 0xff) | ((uint32_t)(q1 & 0xff) << 8) |
                            ((uint32_t)(q2 & 0xff) << 16) | ((uint32_t)q3 << 24);
    }
}

// ---------------------------------------------------------------------------
// Kernel 2: hybrid int8 GEMM. BM=BN=128, BK=64, 4-stage cp.async,
// 80B-padded smem rows, 256 threads, 2 CTAs/SM.
//   warps 0-3: mma.sync (tensor pipe), tile rows 0-63, 2Mx2N warp grid 32x64.
//   warps 4-7: dp4a (fma pipe),       tile rows 64-127, 8x8 per thread.
// ---------------------------------------------------------------------------
#define STAGES 4
#define STAGE_BYTES (2 * 128 * 80)

__global__ __launch_bounds__(256, 2) void gemm_hybrid(const float* __restrict__ bias,
                                                      float* __restrict__ out) {
    constexpr int KT = KK / 64;   // 64 main-loop iterations

    extern __shared__ char sm[];
    __shared__ float s_sw[128];
    __shared__ float s_bias[128];

    const int t = threadIdx.x;
    const int bid = blockIdx.x;
    const int mt = bid >> 5;
    const int nt = bid & 31;
    const int m0 = mt * 128;
    const int n0 = nt * 128;

    if (t < 128) {
        s_sw[t] = g_sw[n0 + t];
        s_bias[t] = bias[n0 + t];
    }

    const int8_t* gA = g_qx + (size_t)m0 * KK;
    const int8_t* gB = g_qw + (size_t)n0 * KK;
    const uint32_t smbase = smem_u32(sm);

    // cp.async mapping: 512 16B chunks per tile, 2 per thread per tile.
    const int crow = t >> 2;
    const int ccol = t & 3;

    auto issue = [&](int it) {
        const int s = it % STAGES;
        const uint32_t sa = smbase + s * STAGE_BYTES;
        const uint32_t sb = sa + 128 * 80;
        const int koff = it * 64 + ccol * 16;
#pragma unroll
        for (int j = 0; j < 2; j++) {
            const int r = crow + j * 64;
            const uint32_t so = (uint32_t)r * 80u + (uint32_t)ccol * 16u;
            CP_ASYNC16(sa + so, gA + (size_t)r * KK + koff);
            CP_ASYNC16(sb + so, gB + (size_t)r * KK + koff);
        }
    };

#pragma unroll
    for (int it = 0; it < STAGES - 1; ++it) {
        issue(it);
        CP_COMMIT();
    }

    const int wid = t >> 5;

    if (wid < 4) {
        // ============ Tensor warps: rows 0-63, 2(M) x 2(N) x (32x64) =========
        const int lane = t & 31;
        const int warpM = wid & 1;
        const int warpN = wid >> 1;

        int acc[2][8][4];
#pragma unroll
        for (int a = 0; a < 2; a++)
#pragma unroll
            for (int b = 0; b < 8; b++)
#pragma unroll
                for (int i = 0; i < 4; i++) acc[a][b][i] = 0;

        const uint32_t a_off =
            (uint32_t)(warpM * 32 + (lane & 15)) * 80u + (uint32_t)(lane >> 4) * 16u;
        const uint32_t b_off =
            (uint32_t)(warpN * 64 + (lane & 7) + ((lane >> 4) & 1) * 8) * 80u +
            (uint32_t)((lane >> 3) & 1) * 16u;

        for (int it = 0; it < KT; ++it) {
            CP_WAIT(STAGES - 2);
            __syncthreads();
            const int nit = it + STAGES - 1;
            if (nit < KT) issue(nit);
            CP_COMMIT();

            const uint32_t sa = smbase + (it % STAGES) * STAGE_BYTES;
            const uint32_t sb = sa + 128 * 80;

#pragma unroll
            for (int s = 0; s < 2; ++s) {
                uint32_t a[2][4];
#pragma unroll
                for (int mtl = 0; mtl < 2; mtl++) {
                    LDSM_X4(a[mtl][0], a[mtl][1], a[mtl][2], a[mtl][3],
                            sa + a_off + (uint32_t)mtl * (16u * 80u) + (uint32_t)s * 32u);
                }
#pragma unroll
                for (int np = 0; np < 4; np++) {
                    uint32_t b0, b1, b2, b3;
                    LDSM_X4(b0, b1, b2, b3,
                            sb + b_off + (uint32_t)np * (16u * 80u) + (uint32_t)s * 32u);
#pragma unroll
                    for (int mtl = 0; mtl < 2; mtl++) {
                        MMA_S8(acc[mtl][2 * np + 0], a[mtl][0], a[mtl][1], a[mtl][2], a[mtl][3], b0, b1);
                        MMA_S8(acc[mtl][2 * np + 1], a[mtl][0], a[mtl][1], a[mtl][2], a[mtl][3], b2, b3);
                    }
                }
            }
        }

        // Epilogue (rows 0-63)
#pragma unroll
        for (int mtl = 0; mtl < 2; mtl++) {
            const int r0 = warpM * 32 + mtl * 16 + (lane >> 2);
            const float sx0 = g_sx[m0 + r0];
            const float sx1 = g_sx[m0 + r0 + 8];
            float* o0 = out + (size_t)(m0 + r0) * NN + n0;
            float* o1 = o0 + (size_t)8 * NN;
#pragma unroll
            for (int ntl = 0; ntl < 8; ntl++) {
                const int lc = warpN * 64 + ntl * 8 + (lane & 3) * 2;
                const float w0 = s_sw[lc], w1 = s_sw[lc + 1];
                const float bb0 = s_bias[lc], bb1 = s_bias[lc + 1];
                float2 v0, v1;
                v0.x = fmaf((float)acc[mtl][ntl][0] * sx0, w0, bb0);
                v0.y = fmaf((float)acc[mtl][ntl][1] * sx0, w1, bb1);
                v1.x = fmaf((float)acc[mtl][ntl][2] * sx1, w0, bb0);
                v1.y = fmaf((float)acc[mtl][ntl][3] * sx1, w1, bb1);
                *reinterpret_cast<float2*>(o0 + lc) = v0;
                *reinterpret_cast<float2*>(o1 + lc) = v1;
            }
        }
    } else {
        // ============ dp4a warps: rows 64-127, 8x8 outputs per thread ========
        // Thread (tr 0..7, tc 0..15): rows 64+tr*8..+8, cols {tc+16c, c=0..7}.
        const int t2 = t - 128;
        const int tr = t2 >> 4;   // 0..7
        const int tc = t2 & 15;   // 0..15

        int acc[8][8];
#pragma unroll
        for (int r = 0; r < 8; r++)
#pragma unroll
            for (int c = 0; c < 8; c++) acc[r][c] = 0;

        for (int it = 0; it < KT; ++it) {
            CP_WAIT(STAGES - 2);
            __syncthreads();
            const int nit = it + STAGES - 1;
            if (nit < KT) issue(nit);
            CP_COMMIT();

            const uint32_t sa_off = (uint32_t)((it % STAGES) * STAGE_BYTES);
            const uint32_t sb_off = sa_off + 128 * 80;

#pragma unroll
            for (int g = 0; g < 4; g++) {   // 4 groups of 16 K-bytes
                uint4 a4[8];
#pragma unroll
                for (int r = 0; r < 8; r++) {
                    a4[r] = *reinterpret_cast<const uint4*>(
                        sm + sa_off + (uint32_t)(64 + tr * 8 + r) * 80u + (uint32_t)g * 16u);
                }
#pragma unroll
                for (int c = 0; c < 8; c++) {
                    const uint4 bv = *reinterpret_cast<const uint4*>(
                        sm + sb_off + (uint32_t)(tc + 16 * c) * 80u + (uint32_t)g * 16u);
#pragma unroll
                    for (int r = 0; r < 8; r++) {
                        int v = __dp4a((int)a4[r].x, (int)bv.x, acc[r][c]);
                        v = __dp4a((int)a4[r].y, (int)bv.y, v);
                        v = __dp4a((int)a4[r].z, (int)bv.z, v);
                        acc[r][c] = __dp4a((int)a4[r].w, (int)bv.w, v);
                    }
                }
            }
        }

        // Epilogue (rows 64-127)
#pragma unroll
        for (int r = 0; r < 8; r++) {
            const int row = m0 + 64 + tr * 8 + r;
            const float sxv = g_sx[row];
            float* orow = out + (size_t)row * NN + n0;
#pragma unroll
            for (int c = 0; c < 8; c++) {
                const int lc = tc + 16 * c;
                orow[lc] = fmaf((float)acc[r][c] * sxv, s_sw[lc], s_bias[lc]);
            }
        }
    }
}

// ---------------------------------------------------------------------------
// Launch
// ---------------------------------------------------------------------------
extern "C" void kernel_launch(void* const* d_in, const int* in_sizes, int n_in,
                              void* d_out, int out_size) {
    const float* x = (const float*)d_in[0];   // [M, 4096]
    const float* w = (const float*)d_in[1];   // [4096, 4096]
    const float* b = (const float*)d_in[2];   // [4096]
    float* out = (float*)d_out;               // [M, 4096]

    const int M = in_sizes[0] / KK;           // 8192

    quant_rows<<<M + NN, 256>>>(x, w, M);

    cudaFuncSetAttribute(gemm_hybrid, cudaFuncAttributeMaxDynamicSharedMemorySize,
                         STAGES * STAGE_BYTES);

    const int total_tiles = (M / 128) * (NN / 128);   // 2048
    gemm_hybrid<<<total_tiles, 256, STAGES * STAGE_BYTES>>>(b, out);
}